// round 15
// baseline (speedup 1.0000x reference)
#include <cuda_runtime.h>
#include <cuda_bf16.h>

// Problem constants
#define BATCH   32768
#define D       768          // 3*16*16 compressed features per sample
#define D4      192          // D/4

__device__ float g_weff[D];

// ---------------------------------------------------------------------------
// Kernel 1: fold lhs/rhs/W into W_eff[768]. Minimal-latency version:
// 6 blocks x 128 threads, ONE output per thread, serial 256-MAC loop.
// W (12KB), lhs, rhs are L2-hot after the first replay -> ~1us total.
// ---------------------------------------------------------------------------
__global__ __launch_bounds__(128)
void fold_weff_kernel(const float* __restrict__ lhs,   // [2,16,8]
                      const float* __restrict__ rhs,   // [2,8,16]
                      const float* __restrict__ W)     // [3072]
{
    const int o   = blockIdx.x * 128 + threadIdx.x;   // 0..767
    const int ch  = o >> 8;
    const int rem = o & 255;
    const int rr  = rem >> 4;
    const int cc  = rem & 15;
    const int r   = rr >> 3;
    const int p   = rr & 7;
    const int c   = cc >> 3;
    const int q   = cc & 7;

    const float* __restrict__ rq = rhs + c * 128 + q * 16;        // [16]
    const float* __restrict__ wb = W + ch * 1024 + c * 16;        // row base
    const float* __restrict__ lb = lhs + r * 128 + p;             // stride 8

    float s = 0.f;
    #pragma unroll
    for (int P = 0; P < 16; P++) {
        const float lv = __ldg(&lb[P * 8]);
        const float* __restrict__ wrow = wb + (r * 16 + P) * 32;
        float inner = 0.f;
        #pragma unroll
        for (int Q = 0; Q < 16; Q++)
            inner = fmaf(__ldg(&rq[Q]), __ldg(&wrow[Q]), inner);
        s = fmaf(lv, inner, s);
    }
    g_weff[o] = s;

#if __CUDA_ARCH__ >= 900
    cudaTriggerProgrammaticLaunchCompletion();
#endif
}

// ---------------------------------------------------------------------------
// Kernel 2 (PDL secondary): out[n] = dot(x[n,:], W_eff) + b.
// Grid-dependency sync at the TOP (don't fight ptxas load placement);
// the node processing + CTA dispatch of this kernel overlaps the fold.
// Body is byte-identical to the proven 16.4us gemv (regs=36).
// ---------------------------------------------------------------------------
__global__ __launch_bounds__(256)
void gemv_kernel(const float4* __restrict__ x,    // [BATCH * D4]
                 const float*  __restrict__ bptr, // [1]
                 float*        __restrict__ out)  // [BATCH]
{
#if __CUDA_ARCH__ >= 900
    cudaGridDependencySynchronize();
#endif

    __shared__ float4 sw[D4];

    const int t = threadIdx.x;
    if (t < D4) sw[t] = reinterpret_cast<const float4*>(g_weff)[t];
    __syncthreads();

    const int warp = t >> 5;
    const int lane = t & 31;
    const int row0 = (blockIdx.x * 8 + warp) * 2;

    const float4* __restrict__ xr0 = x + (size_t)row0 * D4;
    const float4* __restrict__ xr1 = xr0 + D4;

    float4 v0[6], v1[6];
    #pragma unroll
    for (int k = 0; k < 6; k++) v0[k] = xr0[lane + k * 32];
    #pragma unroll
    for (int k = 0; k < 6; k++) v1[k] = xr1[lane + k * 32];

    float a0 = 0.f, a1 = 0.f;
    #pragma unroll
    for (int k = 0; k < 6; k++) {
        const float4 w = sw[lane + k * 32];
        a0 = fmaf(v0[k].x, w.x, a0);
        a0 = fmaf(v0[k].y, w.y, a0);
        a0 = fmaf(v0[k].z, w.z, a0);
        a0 = fmaf(v0[k].w, w.w, a0);
        a1 = fmaf(v1[k].x, w.x, a1);
        a1 = fmaf(v1[k].y, w.y, a1);
        a1 = fmaf(v1[k].z, w.z, a1);
        a1 = fmaf(v1[k].w, w.w, a1);
    }

    #pragma unroll
    for (int off = 16; off > 0; off >>= 1) {
        a0 += __shfl_xor_sync(0xFFFFFFFFu, a0, off);
        a1 += __shfl_xor_sync(0xFFFFFFFFu, a1, off);
    }

    if (lane == 0) {
        const float bb = bptr[0];
        out[row0]     = a0 + bb;
        out[row0 + 1] = a1 + bb;
    }
}

// ---------------------------------------------------------------------------
extern "C" void kernel_launch(void* const* d_in, const int* in_sizes, int n_in,
                              void* d_out, int out_size)
{
    const float* x   = (const float*)d_in[0];   // [32768, 3, 16, 16]
    const float* lhs = (const float*)d_in[1];   // [2, 16, 8]
    const float* rhs = (const float*)d_in[2];   // [2, 8, 16]
    const float* W   = (const float*)d_in[3];   // [1, 3072]
    const float* b   = (const float*)d_in[4];   // [1]
    float* out       = (float*)d_out;           // [32768]

    // Primary: minimal fold (6 blocks x 128 threads)
    fold_weff_kernel<<<6, 128>>>(lhs, rhs, W);

    // Secondary: gemv, PDL so its dispatch overlaps the fold's execution.
    cudaLaunchConfig_t cfg = {};
    cfg.gridDim  = dim3(BATCH / 16);   // 2048
    cfg.blockDim = dim3(256);
    cfg.dynamicSmemBytes = 0;
    cfg.stream = 0;

    cudaLaunchAttribute attrs[1];
    attrs[0].id = cudaLaunchAttributeProgrammaticStreamSerialization;
    attrs[0].val.programmaticStreamSerializationAllowed = 1;
    cfg.attrs    = attrs;
    cfg.numAttrs = 1;

    cudaLaunchKernelEx(&cfg, gemv_kernel,
                       (const float4*)x, (const float*)b, (float*)out);
}

// round 16
// speedup vs baseline: 1.4762x; 1.4762x over previous
#include <cuda_runtime.h>
#include <cuda_bf16.h>

// Problem constants
#define BATCH   32768
#define D       768          // 3*16*16 compressed features per sample
#define D4      192          // D/4

__device__ float g_weff[D];

// ---------------------------------------------------------------------------
// Kernel 1: fold lhs/rhs/W into W_eff[768]. R13's proven-fast shape:
// one block per output, 256 threads = one MAC each + tree reduce.
// Duration is launch-wave-bound (~1.3us), fully parallel.
// ---------------------------------------------------------------------------
__global__ void fold_weff_kernel(const float* __restrict__ lhs,   // [2,16,8]
                                 const float* __restrict__ rhs,   // [2,8,16]
                                 const float* __restrict__ W)     // [3072]
{
    const int o   = blockIdx.x;          // 0..767
    const int ch  = o >> 8;
    const int rem = o & 255;
    const int rr  = rem >> 4;
    const int cc  = rem & 15;
    const int r   = rr >> 3;
    const int p   = rr & 7;
    const int c   = cc >> 3;
    const int q   = cc & 7;

    const int t = threadIdx.x;           // 0..255
    const int P = t >> 4;
    const int Q = t & 15;

    float term = lhs[r * 128 + P * 8 + p]
               * rhs[c * 128 + q * 16 + Q]
               * W[ch * 1024 + (r * 16 + P) * 32 + (c * 16 + Q)];

    #pragma unroll
    for (int off = 16; off > 0; off >>= 1)
        term += __shfl_xor_sync(0xFFFFFFFFu, term, off);

    __shared__ float warp_sums[8];
    const int lane = t & 31;
    const int wid  = t >> 5;
    if (lane == 0) warp_sums[wid] = term;
    __syncthreads();

    if (t == 0) {
        float s = 0.f;
        #pragma unroll
        for (int w = 0; w < 8; w++) s += warp_sums[w];
        g_weff[o] = s;
    }
#if __CUDA_ARCH__ >= 900
    cudaTriggerProgrammaticLaunchCompletion();
#endif
}

// ---------------------------------------------------------------------------
// Kernel 2 (PDL secondary): out[n] = dot(x[n,:], W_eff) + b.
// Grid sync as the FIRST statement (R15 verified this leaves codegen intact:
// regs=36). Body is byte-identical to the proven 16.4us gemv.
// ---------------------------------------------------------------------------
__global__ __launch_bounds__(256)
void gemv_kernel(const float4* __restrict__ x,    // [BATCH * D4]
                 const float*  __restrict__ bptr, // [1]
                 float*        __restrict__ out)  // [BATCH]
{
#if __CUDA_ARCH__ >= 900
    cudaGridDependencySynchronize();
#endif

    __shared__ float4 sw[D4];

    const int t = threadIdx.x;
    if (t < D4) sw[t] = reinterpret_cast<const float4*>(g_weff)[t];
    __syncthreads();

    const int warp = t >> 5;
    const int lane = t & 31;
    const int row0 = (blockIdx.x * 8 + warp) * 2;

    const float4* __restrict__ xr0 = x + (size_t)row0 * D4;
    const float4* __restrict__ xr1 = xr0 + D4;

    float4 v0[6], v1[6];
    #pragma unroll
    for (int k = 0; k < 6; k++) v0[k] = xr0[lane + k * 32];
    #pragma unroll
    for (int k = 0; k < 6; k++) v1[k] = xr1[lane + k * 32];

    float a0 = 0.f, a1 = 0.f;
    #pragma unroll
    for (int k = 0; k < 6; k++) {
        const float4 w = sw[lane + k * 32];
        a0 = fmaf(v0[k].x, w.x, a0);
        a0 = fmaf(v0[k].y, w.y, a0);
        a0 = fmaf(v0[k].z, w.z, a0);
        a0 = fmaf(v0[k].w, w.w, a0);
        a1 = fmaf(v1[k].x, w.x, a1);
        a1 = fmaf(v1[k].y, w.y, a1);
        a1 = fmaf(v1[k].z, w.z, a1);
        a1 = fmaf(v1[k].w, w.w, a1);
    }

    #pragma unroll
    for (int off = 16; off > 0; off >>= 1) {
        a0 += __shfl_xor_sync(0xFFFFFFFFu, a0, off);
        a1 += __shfl_xor_sync(0xFFFFFFFFu, a1, off);
    }

    if (lane == 0) {
        const float bb = bptr[0];
        out[row0]     = a0 + bb;
        out[row0 + 1] = a1 + bb;
    }
}

// ---------------------------------------------------------------------------
extern "C" void kernel_launch(void* const* d_in, const int* in_sizes, int n_in,
                              void* d_out, int out_size)
{
    const float* x   = (const float*)d_in[0];   // [32768, 3, 16, 16]
    const float* lhs = (const float*)d_in[1];   // [2, 16, 8]
    const float* rhs = (const float*)d_in[2];   // [2, 8, 16]
    const float* W   = (const float*)d_in[3];   // [1, 3072]
    const float* b   = (const float*)d_in[4];   // [1]
    float* out       = (float*)d_out;           // [32768]

    // Primary: full-parallelism fold (768 blocks x 256 threads, ~1.3us)
    fold_weff_kernel<<<D, 256>>>(lhs, rhs, W);

    // Secondary: golden gemv, PDL so its dispatch overlaps the fold.
    cudaLaunchConfig_t cfg = {};
    cfg.gridDim  = dim3(BATCH / 16);   // 2048
    cfg.blockDim = dim3(256);
    cfg.dynamicSmemBytes = 0;
    cfg.stream = 0;

    cudaLaunchAttribute attrs[1];
    attrs[0].id = cudaLaunchAttributeProgrammaticStreamSerialization;
    attrs[0].val.programmaticStreamSerializationAllowed = 1;
    cfg.attrs    = attrs;
    cfg.numAttrs = 1;

    cudaLaunchKernelEx(&cfg, gemv_kernel,
                       (const float4*)x, (const float*)b, (float*)out);
}

// round 17
// speedup vs baseline: 1.4904x; 1.0096x over previous
#include <cuda_runtime.h>
#include <cuda_bf16.h>

// Problem constants
#define BATCH   32768
#define D       768          // 3*16*16 compressed features per sample
#define D4      192          // D/4
#define D8      96           // D/8 (32-byte chunks per row)

__device__ float g_weff[D];

// ---------------------------------------------------------------------------
// Kernel 1: fold lhs/rhs/W into W_eff[768]. Proven-fast shape:
// one block per output, 256 threads = one MAC each + tree reduce.
// ---------------------------------------------------------------------------
__global__ void fold_weff_kernel(const float* __restrict__ lhs,   // [2,16,8]
                                 const float* __restrict__ rhs,   // [2,8,16]
                                 const float* __restrict__ W)     // [3072]
{
    const int o   = blockIdx.x;          // 0..767
    const int ch  = o >> 8;
    const int rem = o & 255;
    const int rr  = rem >> 4;
    const int cc  = rem & 15;
    const int r   = rr >> 3;
    const int p   = rr & 7;
    const int c   = cc >> 3;
    const int q   = cc & 7;

    const int t = threadIdx.x;           // 0..255
    const int P = t >> 4;
    const int Q = t & 15;

    float term = lhs[r * 128 + P * 8 + p]
               * rhs[c * 128 + q * 16 + Q]
               * W[ch * 1024 + (r * 16 + P) * 32 + (c * 16 + Q)];

    #pragma unroll
    for (int off = 16; off > 0; off >>= 1)
        term += __shfl_xor_sync(0xFFFFFFFFu, term, off);

    __shared__ float warp_sums[8];
    const int lane = t & 31;
    const int wid  = t >> 5;
    if (lane == 0) warp_sums[wid] = term;
    __syncthreads();

    if (t == 0) {
        float s = 0.f;
        #pragma unroll
        for (int w = 0; w < 8; w++) s += warp_sums[w];
        g_weff[o] = s;
    }
}

// 256-bit global load (sm_100a): one LDG.E.256 brings 32 bytes per lane.
struct f8 { float4 a, b; };
__device__ __forceinline__ f8 ldg256(const float* p) {
    f8 r;
    asm volatile("ld.global.v8.f32 {%0,%1,%2,%3,%4,%5,%6,%7}, [%8];"
                 : "=f"(r.a.x), "=f"(r.a.y), "=f"(r.a.z), "=f"(r.a.w),
                   "=f"(r.b.x), "=f"(r.b.y), "=f"(r.b.z), "=f"(r.b.w)
                 : "l"(p));
    return r;
}

// ---------------------------------------------------------------------------
// Kernel 2: out[n] = dot(x[n,:], W_eff) + b.
// 8 warps x 2 rows = 16 rows/block. Each lane reads 32B/row/iter via v8
// loads (3 iters cover the 768-float row). Weights live in two stride-1
// float4 smem arrays (conflict-free for the paired reads).
// ---------------------------------------------------------------------------
__global__ __launch_bounds__(256)
void gemv_kernel(const float* __restrict__ x,    // [BATCH * D]
                 const float* __restrict__ bptr, // [1]
                 float*       __restrict__ out)  // [BATCH]
{
    __shared__ float4 swA[D8];   // first half of each 32B chunk
    __shared__ float4 swB[D8];   // second half

    const int t = threadIdx.x;
    if (t < D8) {
        const float4* w4 = reinterpret_cast<const float4*>(g_weff);
        swA[t] = w4[2 * t];
        swB[t] = w4[2 * t + 1];
    }
    __syncthreads();

    const int warp = t >> 5;
    const int lane = t & 31;
    const int row0 = (blockIdx.x * 8 + warp) * 2;

    const float* __restrict__ xr0 = x + (size_t)row0 * D;
    const float* __restrict__ xr1 = xr0 + D;

    float a0 = 0.f, a1 = 0.f;
    #pragma unroll
    for (int k = 0; k < 3; k++) {
        const int c = lane + k * 32;             // chunk index 0..95
        const f8 v0 = ldg256(xr0 + c * 8);
        const f8 v1 = ldg256(xr1 + c * 8);
        const float4 wA = swA[c];
        const float4 wB = swB[c];

        a0 = fmaf(v0.a.x, wA.x, a0); a0 = fmaf(v0.a.y, wA.y, a0);
        a0 = fmaf(v0.a.z, wA.z, a0); a0 = fmaf(v0.a.w, wA.w, a0);
        a0 = fmaf(v0.b.x, wB.x, a0); a0 = fmaf(v0.b.y, wB.y, a0);
        a0 = fmaf(v0.b.z, wB.z, a0); a0 = fmaf(v0.b.w, wB.w, a0);

        a1 = fmaf(v1.a.x, wA.x, a1); a1 = fmaf(v1.a.y, wA.y, a1);
        a1 = fmaf(v1.a.z, wA.z, a1); a1 = fmaf(v1.a.w, wA.w, a1);
        a1 = fmaf(v1.b.x, wB.x, a1); a1 = fmaf(v1.b.y, wB.y, a1);
        a1 = fmaf(v1.b.z, wB.z, a1); a1 = fmaf(v1.b.w, wB.w, a1);
    }

    #pragma unroll
    for (int off = 16; off > 0; off >>= 1) {
        a0 += __shfl_xor_sync(0xFFFFFFFFu, a0, off);
        a1 += __shfl_xor_sync(0xFFFFFFFFu, a1, off);
    }

    if (lane == 0) {
        const float bb = bptr[0];
        out[row0]     = a0 + bb;
        out[row0 + 1] = a1 + bb;
    }
}

// ---------------------------------------------------------------------------
extern "C" void kernel_launch(void* const* d_in, const int* in_sizes, int n_in,
                              void* d_out, int out_size)
{
    const float* x   = (const float*)d_in[0];   // [32768, 3, 16, 16]
    const float* lhs = (const float*)d_in[1];   // [2, 16, 8]
    const float* rhs = (const float*)d_in[2];   // [2, 8, 16]
    const float* W   = (const float*)d_in[3];   // [1, 3072]
    const float* b   = (const float*)d_in[4];   // [1]
    float* out       = (float*)d_out;           // [32768]

    fold_weff_kernel<<<D, 256>>>(lhs, rhs, W);

    // 16 rows per block -> 2048 blocks
    gemv_kernel<<<BATCH / 16, 256>>>(x, b, out);
}